// round 11
// baseline (speedup 1.0000x reference)
#include <cuda_runtime.h>

#define N_TRAJ  256
#define T_LEN   1024
#define K_TYPES 1000
#define D_EMB   64
#define EPS     1e-8f

#define N_ROWS      (N_TRAJ * T_LEN)                   // 262144
#define EMB_TOTAL   (N_ROWS * D_EMB)                   // 16777216
#define EMB_BULK4   ((EMB_TOTAL - 4) / 4)              // 4194303 quads at pos 3+4q
#define QPT         4                                  // quads per thread
#define QUADS_PER_BLOCK (256 * QPT)                    // 1024 quads = 64 rows
#define EMB_BLOCKS  4096                               // 64 rows per block, exact

__device__ int g_reduce_ctr;   // zero-init; reset at end of each launch

// ---------------------------------------------------------------------------
// Fused kernel:
//   blocks [0, 256)          : per-trajectory reduction (4 events/thread,
//                              batched gathers); last-done block folds the
//                              scalar sum deterministically.
//   blocks [256, 256+4096)   : embedding gather with MINIMAL L2 traffic:
//                              stage the block's 64 table rows ONCE in smem
//                              (coalesced LDG.128, 16KB = output size), then
//                              compose rotated quads from smem (2 aligned
//                              LDS.128, branchless) and STG.128 __stcs.
// ---------------------------------------------------------------------------
__global__ void fused_kernel(const int* __restrict__ event_types,
                             const float* __restrict__ prob_event,
                             const float* __restrict__ intensities,
                             const float* __restrict__ Lambda,
                             const float* __restrict__ input_mask,
                             const float* __restrict__ type_table,
                             float* __restrict__ out,
                             float* __restrict__ out_emb) {
    const int tid = threadIdx.x;

    if (blockIdx.x < N_TRAJ) {
        // ---------------- reduction path (R6 structure, best known) ----------------
        const int n = blockIdx.x;
        const int base = n * T_LEN;

        float m[4], inz[4], p[4];
        #pragma unroll
        for (int i = 0; i < 4; i++) {
            const int t = base + tid + i * 256;
            m[i]   = input_mask[t];
            inz[i] = intensities[t];
            const int e = event_types[t];
            p[i] = __ldcs(&prob_event[(long long)t * K_TYPES + e]);
        }

        float ev = 0.0f, tm = 0.0f;
        #pragma unroll
        for (int i = 0; i < 4; i++) {
            tm = fmaf(__logf(inz[i] + EPS), m[i], tm);
            ev = fmaf(__logf(p[i]   + EPS), m[i], ev);
        }

        __shared__ float s_ev[256];
        __shared__ float s_tm[256];
        s_ev[tid] = ev;
        s_tm[tid] = tm;
        __syncthreads();

        #pragma unroll
        for (int s = 128; s > 0; s >>= 1) {
            if (tid < s) {
                s_ev[tid] += s_ev[tid + s];
                s_tm[tid] += s_tm[tid + s];
            }
            __syncthreads();
        }

        if (tid == 0) {
            const float tnt = s_tm[0] - Lambda[n];
            out[n]              = tnt + s_ev[0];   // ll_N
            out[N_TRAJ + 1 + n] = tnt;             // time_loglik_NT
        }

        __threadfence();
        __shared__ int is_last;
        if (tid == 0) {
            const int v = atomicAdd(&g_reduce_ctr, 1);
            is_last = (v == N_TRAJ - 1);
        }
        __syncthreads();
        if (is_last) {
            __threadfence();
            s_ev[tid] = out[tid];
            __syncthreads();
            #pragma unroll
            for (int s = 128; s > 0; s >>= 1) {
                if (tid < s) s_ev[tid] += s_ev[tid + s];
                __syncthreads();
            }
            if (tid == 0) {
                out[N_TRAJ] = s_ev[0];              // time_loglik
                g_reduce_ctr = 0;                   // reset for graph replay
            }
        }
        return;
    }

    // ---------------- embedding path ----------------
    const int b = blockIdx.x - N_TRAJ;                 // 0 .. 4095

    __shared__ __align__(16) float s_tab[64 * D_EMB + 4];  // 64 rows + row64 head
    __shared__ int s_idx[68];                               // padded (16B multiple)

    if (tid < 65) {
        const int r = 64 * b + tid;
        s_idx[tid] = (r < N_ROWS) ? event_types[r] : 0;
    }
    __syncthreads();

    // Stage: each table row read EXACTLY ONCE, perfectly coalesced LDG.128.
    // i = tid + 256k : row = i>>4, float4-col = i&15.
    #pragma unroll
    for (int k = 0; k < QPT; k++) {
        const int i = tid + 256 * k;
        const int r = i >> 4;
        const int c = (i & 15) * 4;
        const int e = s_idx[r];
        const float4 f = __ldg((const float4*)(type_table + e * D_EMB + c));
        *(float4*)(s_tab + r * D_EMB + c) = f;
    }
    if (tid == 0) {
        // first float4 of row 64 (for the tile's 3-float overhang)
        const int e64 = s_idx[64];
        *(float4*)(s_tab + 64 * D_EMB) = __ldg((const float4*)(type_table + e64 * D_EMB));
    }
    __syncthreads();

    // Compose + store: staged rows are contiguous, so emb[pos] = s_tab[pos-4096b].
    // Quad at pos (pos ≡ 3 mod 4): two 16B-aligned LDS.128 at o-3 / o+1, branchless.
    const int obase = b * QUADS_PER_BLOCK + tid;
    float4 lo[QPT], hi[QPT];
    int    pos[QPT];
    bool   ok[QPT];

    #pragma unroll
    for (int k = 0; k < QPT; k++) {
        const int q = obase + 256 * k;
        ok[k]  = (q < EMB_BULK4);                      // only very last quad fails
        pos[k] = 3 + 4 * q;
        const int o = pos[k] - 4096 * b;               // 3 .. 4095 (hi reaches 4099)
        lo[k] = *(const float4*)(s_tab + (o - 3));     // (o-3) % 4 == 0
        hi[k] = *(const float4*)(s_tab + (o + 1));     // (o+1) % 4 == 0
    }

    #pragma unroll
    for (int k = 0; k < QPT; k++) {
        if (ok[k]) {
            float4 v;
            v.x = lo[k].w; v.y = hi[k].x; v.z = hi[k].y; v.w = hi[k].z;
            __stcs(reinterpret_cast<float4*>(out_emb + pos[k]), v);
        }
    }

    if (b == 0 && tid == 0) {
        // head: emb pos 0,1,2 (row 0)
        out_emb[0] = s_tab[0];
        out_emb[1] = s_tab[1];
        out_emb[2] = s_tab[2];
    }
    if (b == EMB_BLOCKS - 1 && tid == 1) {
        // tail: emb pos EMB_TOTAL-1 = last float of row 63 of the last block
        out_emb[EMB_TOTAL - 1] = s_tab[63 * D_EMB + (D_EMB - 1)];
    }
}

extern "C" void kernel_launch(void* const* d_in, const int* in_sizes, int n_in,
                              void* d_out, int out_size) {
    const int*   event_types = (const int*)  d_in[0];   // (N, T) int32
    const float* prob_event  = (const float*)d_in[1];   // (N, T, K)
    const float* intensities = (const float*)d_in[2];   // (N, T)
    const float* Lambda      = (const float*)d_in[3];   // (N,)
    const float* input_mask  = (const float*)d_in[4];   // (N, T)
    const float* type_table  = (const float*)d_in[5];   // (K, D)

    float* out = (float*)d_out;
    // Layout: [ll_N (256)] [time_loglik (1)] [time_loglik_NT (256)] [type_emb]
    float* out_emb = out + (N_TRAJ + 1 + N_TRAJ);

    fused_kernel<<<N_TRAJ + EMB_BLOCKS, 256>>>(event_types, prob_event,
                                               intensities, Lambda, input_mask,
                                               type_table, out, out_emb);
}

// round 12
// speedup vs baseline: 1.2222x; 1.2222x over previous
#include <cuda_runtime.h>

#define N_TRAJ  256
#define T_LEN   1024
#define K_TYPES 1000
#define D_EMB   64
#define EPS     1e-8f

#define N_ROWS      (N_TRAJ * T_LEN)                   // 262144
#define EMB_TOTAL   (N_ROWS * D_EMB)                   // 16777216
#define EMB_BULK4   ((EMB_TOTAL - 4) / 4)              // 4194303 quads at pos 3+4q
#define QPT         4                                  // quads per phase per thread
#define PHASES      2                                  // 2 phases -> 128 rows/block
#define ROWS_PER_BLOCK 128
#define QUADS_PER_BLOCK (256 * QPT * PHASES)           // 2048 quads = 128 rows
#define EMB_BLOCKS  (N_ROWS / ROWS_PER_BLOCK)          // 2048

__device__ int g_reduce_ctr;   // zero-init; reset at end of each launch

// ---------------------------------------------------------------------------
// Fused kernel:
//   blocks [0, 256)          : per-trajectory reduction (4 events/thread,
//                              batched gathers); last-done block folds the
//                              scalar sum deterministically.
//   blocks [256, 256+2048)   : embedding gather, 128 rows/block in 2 phases.
//                              Per phase: 8 batched LDG.128 (overlapping
//                              aligned lo/hi reads, mostly L1 hits) then
//                              4 coalesced STG.128 __stcs. No smem staging —
//                              minimal MIO op count (R6 structure).
// ---------------------------------------------------------------------------
__global__ void fused_kernel(const int* __restrict__ event_types,
                             const float* __restrict__ prob_event,
                             const float* __restrict__ intensities,
                             const float* __restrict__ Lambda,
                             const float* __restrict__ input_mask,
                             const float* __restrict__ type_table,
                             float* __restrict__ out,
                             float* __restrict__ out_emb) {
    const int tid = threadIdx.x;

    if (blockIdx.x < N_TRAJ) {
        // ---------------- reduction path (R6 structure, best known) ----------------
        const int n = blockIdx.x;
        const int base = n * T_LEN;

        float m[4], inz[4], p[4];
        #pragma unroll
        for (int i = 0; i < 4; i++) {
            const int t = base + tid + i * 256;
            m[i]   = input_mask[t];
            inz[i] = intensities[t];
            const int e = event_types[t];
            p[i] = __ldcs(&prob_event[(long long)t * K_TYPES + e]);
        }

        float ev = 0.0f, tm = 0.0f;
        #pragma unroll
        for (int i = 0; i < 4; i++) {
            tm = fmaf(__logf(inz[i] + EPS), m[i], tm);
            ev = fmaf(__logf(p[i]   + EPS), m[i], ev);
        }

        __shared__ float s_ev[256];
        __shared__ float s_tm[256];
        s_ev[tid] = ev;
        s_tm[tid] = tm;
        __syncthreads();

        #pragma unroll
        for (int s = 128; s > 0; s >>= 1) {
            if (tid < s) {
                s_ev[tid] += s_ev[tid + s];
                s_tm[tid] += s_tm[tid + s];
            }
            __syncthreads();
        }

        if (tid == 0) {
            const float tnt = s_tm[0] - Lambda[n];
            out[n]              = tnt + s_ev[0];   // ll_N
            out[N_TRAJ + 1 + n] = tnt;             // time_loglik_NT
        }

        __threadfence();
        __shared__ int is_last;
        if (tid == 0) {
            const int v = atomicAdd(&g_reduce_ctr, 1);
            is_last = (v == N_TRAJ - 1);
        }
        __syncthreads();
        if (is_last) {
            __threadfence();
            s_ev[tid] = out[tid];
            __syncthreads();
            #pragma unroll
            for (int s = 128; s > 0; s >>= 1) {
                if (tid < s) s_ev[tid] += s_ev[tid + s];
                __syncthreads();
            }
            if (tid == 0) {
                out[N_TRAJ] = s_ev[0];              // time_loglik
                g_reduce_ctr = 0;                   // reset for graph replay
            }
        }
        return;
    }

    // ---------------- embedding path ----------------
    const int b = blockIdx.x - N_TRAJ;                 // 0 .. 2047

    // Stage the 129 event indices this block needs (rows 128b .. 128b+128).
    __shared__ int s_idx[129];
    if (tid < 129) {
        const int r = ROWS_PER_BLOCK * b + tid;
        s_idx[tid] = (r < N_ROWS) ? event_types[r] : 0;
    }
    __syncthreads();

    #pragma unroll
    for (int ph = 0; ph < PHASES; ph++) {
        const int qbase = b * QUADS_PER_BLOCK + ph * (256 * QPT) + tid;

        int    pos[QPT];
        bool   ok[QPT];
        float4 lo[QPT], hi[QPT];

        // Phase A: address math + issue all 8 independent LDG.128s.
        #pragma unroll
        for (int k = 0; k < QPT; k++) {
            const int q = qbase + k * 256;
            ok[k]  = (q < EMB_BULK4);              // only very last quad fails
            pos[k] = 3 + 4 * q;
            const int lrow = (pos[k] >> 6) - ROWS_PER_BLOCK * b;   // 0..127
            const int d    = pos[k] & (D_EMB - 1);                 // 3,7,...,63

            const int e  = s_idx[lrow];
            const int eb = (d == D_EMB - 1) ? s_idx[lrow + 1] : e;
            const int o  = (d == D_EMB - 1) ? 0 : d + 1;

            if (ok[k]) {
                lo[k] = __ldg((const float4*)(type_table + e  * D_EMB + (d - 3)));
                hi[k] = __ldg((const float4*)(type_table + eb * D_EMB + o));
            }
        }

        // Phase B: recombine + streaming coalesced stores.
        #pragma unroll
        for (int k = 0; k < QPT; k++) {
            if (ok[k]) {
                float4 v;
                v.x = lo[k].w; v.y = hi[k].x; v.z = hi[k].y; v.w = hi[k].z;
                __stcs(reinterpret_cast<float4*>(out_emb + pos[k]), v);
            }
        }
    }

    if (b == 0 && tid == 0) {
        // head pos 0,1,2 (row 0) and tail pos EMB_TOTAL-1
        const int eh = s_idx[0];
        out_emb[0] = __ldg(&type_table[eh * D_EMB + 0]);
        out_emb[1] = __ldg(&type_table[eh * D_EMB + 1]);
        out_emb[2] = __ldg(&type_table[eh * D_EMB + 2]);
        const int lrow = (EMB_TOTAL - 1) >> 6;
        const int el = __ldg(&event_types[lrow]);
        out_emb[EMB_TOTAL - 1] = __ldg(&type_table[el * D_EMB + (D_EMB - 1)]);
    }
}

extern "C" void kernel_launch(void* const* d_in, const int* in_sizes, int n_in,
                              void* d_out, int out_size) {
    const int*   event_types = (const int*)  d_in[0];   // (N, T) int32
    const float* prob_event  = (const float*)d_in[1];   // (N, T, K)
    const float* intensities = (const float*)d_in[2];   // (N, T)
    const float* Lambda      = (const float*)d_in[3];   // (N,)
    const float* input_mask  = (const float*)d_in[4];   // (N, T)
    const float* type_table  = (const float*)d_in[5];   // (K, D)

    float* out = (float*)d_out;
    // Layout: [ll_N (256)] [time_loglik (1)] [time_loglik_NT (256)] [type_emb]
    float* out_emb = out + (N_TRAJ + 1 + N_TRAJ);

    fused_kernel<<<N_TRAJ + EMB_BLOCKS, 256>>>(event_types, prob_event,
                                               intensities, Lambda, input_mask,
                                               type_table, out, out_emb);
}